// round 4
// baseline (speedup 1.0000x reference)
#include <cuda_runtime.h>
#include <cstdint>

#define D_IN  256
#define D_OUT 64
#define ROWS_TOTAL 200000   // N*K = 50000*4

// Scratch for support = x @ W  (51.2 MB, static device global: allowed)
__device__ float g_support[(size_t)ROWS_TOTAL * D_OUT];

// ---------------------------------------------------------------------------
// packed f32x2 helpers (sm_100+ PTX)
// ---------------------------------------------------------------------------
__device__ __forceinline__ unsigned long long pack2(float a, float b) {
    unsigned long long r;
    asm("mov.b64 %0, {%1, %2};" : "=l"(r) : "f"(a), "f"(b));
    return r;
}
__device__ __forceinline__ void fma2(unsigned long long& acc,
                                     unsigned long long a,
                                     unsigned long long b) {
    asm("fma.rn.f32x2 %0, %1, %2, %0;" : "+l"(acc) : "l"(a), "l"(b));
}

// ---------------------------------------------------------------------------
// Kernel 1: support[row][0:64] = x[row][0:256] @ W   (one row per thread)
// W staged in smem in two 128-row halves (32 KB), read as double2 so each
// LDS.128 yields two ready-made f32x2 operands (no repack instructions).
// ---------------------------------------------------------------------------
__global__ void __launch_bounds__(128)
gemm_kernel(const float* __restrict__ x, const float* __restrict__ w, int rows)
{
    __shared__ __align__(16) float ws[128 * D_OUT];   // 32 KB

    const int row = blockIdx.x * 128 + threadIdx.x;

    unsigned long long acc[32];
#pragma unroll
    for (int i = 0; i < 32; ++i) acc[i] = 0ull;

    for (int half = 0; half < 2; ++half) {
        // cooperative load of W rows [half*128, half*128+128)
        const float4* wsrc = (const float4*)(w + (size_t)half * 128 * D_OUT);
        float4*       wdst = (float4*)ws;
        for (int i = threadIdx.x; i < 128 * D_OUT / 4; i += 128)
            wdst[i] = wsrc[i];
        __syncthreads();

        if (row < rows) {
            const float4* xr = (const float4*)(x + (size_t)row * D_IN) + half * 32;
#pragma unroll 1
            for (int d4 = 0; d4 < 32; ++d4) {
                const float4 xv = xr[d4];
#pragma unroll
                for (int s = 0; s < 4; ++s) {
                    const float xs = (s == 0) ? xv.x : (s == 1) ? xv.y
                                   : (s == 2) ? xv.z : xv.w;
                    const unsigned long long xp = pack2(xs, xs);
                    const double2* wrow = (const double2*)(ws + (d4 * 4 + s) * D_OUT);
#pragma unroll
                    for (int q = 0; q < 16; ++q) {
                        const double2 wv = wrow[q];   // LDS.128, broadcast
                        fma2(acc[2 * q + 0], xp, __double_as_longlong(wv.x));
                        fma2(acc[2 * q + 1], xp, __double_as_longlong(wv.y));
                    }
                }
            }
        }
        __syncthreads();
    }

    if (row < rows) {
        double* sup = (double*)(g_support + (size_t)row * D_OUT);
#pragma unroll
        for (int q = 0; q < 32; ++q)
            sup[q] = __longlong_as_double(acc[q]);    // bitwise 2x f32 store
    }
}

// ---------------------------------------------------------------------------
// Kernel 2: zero d_out
// ---------------------------------------------------------------------------
__global__ void zero_kernel(float4* __restrict__ out, int n4)
{
    int i = blockIdx.x * blockDim.x + threadIdx.x;
    if (i < n4) out[i] = make_float4(0.f, 0.f, 0.f, 0.f);
}

// ---------------------------------------------------------------------------
// Kernel 3: scatter-add. One thread per (edge, float4-chunk-of-256-floats).
// 64 consecutive threads share one edge -> per-warp-uniform index loads and
// fully coalesced 1 KB gather of support[col]. Vector RED (16B) accumulate.
// ---------------------------------------------------------------------------
__global__ void __launch_bounds__(256)
scatter_kernel(const int* __restrict__ adj_rows, const int* __restrict__ adj_cols,
               const float* __restrict__ adj_vals, float* __restrict__ out, int E)
{
    const long long gid = (long long)blockIdx.x * 256 + threadIdx.x;
    const int e = (int)(gid >> 6);
    if (e >= E) return;
    const int j = (int)(gid & 63);

    const int   r = __ldg(adj_rows + e);
    const int   c = __ldg(adj_cols + e);
    const float v = __ldg(adj_vals + e);

    const float4 s = ((const float4*)(g_support + (size_t)c * 256))[j];
    float* dst = out + (size_t)r * 256 + j * 4;
    asm volatile("red.global.add.v4.f32 [%0], {%1, %2, %3, %4};"
                 :: "l"(dst), "f"(s.x * v), "f"(s.y * v), "f"(s.z * v), "f"(s.w * v)
                 : "memory");
}

// ---------------------------------------------------------------------------
// Kernel 4: in-place ReLU
// ---------------------------------------------------------------------------
__global__ void relu_kernel(float4* __restrict__ out, int n4)
{
    int i = blockIdx.x * blockDim.x + threadIdx.x;
    if (i < n4) {
        float4 v = out[i];
        v.x = fmaxf(v.x, 0.f); v.y = fmaxf(v.y, 0.f);
        v.z = fmaxf(v.z, 0.f); v.w = fmaxf(v.w, 0.f);
        out[i] = v;
    }
}

// ---------------------------------------------------------------------------
// Launch
// inputs (metadata order): x[f32], weight[f32], adj_rows[i32], adj_cols[i32],
//                          adj_vals[f32]; output f32 [N,K,64]
// ---------------------------------------------------------------------------
extern "C" void kernel_launch(void* const* d_in, const int* in_sizes, int n_in,
                              void* d_out, int out_size)
{
    const float* x  = (const float*)d_in[0];
    const float* w  = (const float*)d_in[1];
    const int*   ar = (const int*)d_in[2];
    const int*   ac = (const int*)d_in[3];
    const float* av = (const float*)d_in[4];
    float*       out = (float*)d_out;

    const int rows = in_sizes[0] / D_IN;   // 200000
    const int E    = in_sizes[2];          // 800000
    const int n4   = out_size / 4;         // 3.2M float4

    zero_kernel<<<(n4 + 255) / 256, 256>>>((float4*)out, n4);
    gemm_kernel<<<(rows + 127) / 128, 128>>>(x, w, rows);

    const long long nthreads = (long long)E * 64;
    scatter_kernel<<<(int)((nthreads + 255) / 256), 256>>>(ar, ac, av, out, E);

    relu_kernel<<<(n4 + 255) / 256, 256>>>((float4*)out, n4);
}

// round 5
// speedup vs baseline: 1.3317x; 1.3317x over previous
#include <cuda_runtime.h>
#include <cstdint>

#define D_IN  256
#define D_OUT 64
#define ROWS_TOTAL 200000   // N*K = 50000*4
#define NMAX  50048         // padded N
#define EMAX  800000

// ---------------------------------------------------------------------------
// Static device scratch (allocation-free rule)
// ---------------------------------------------------------------------------
__device__ float g_support[(size_t)ROWS_TOTAL * D_OUT];  // 51.2 MB
__device__ int   g_deg[NMAX];
__device__ int   g_start[NMAX + 1];
__device__ int   g_cursor[NMAX];
__device__ int2  g_edges[EMAX];      // {col, val_bits} interleaved for locality
__device__ int   g_part[1024];
__device__ int   g_pscan[1024];

// ---------------------------------------------------------------------------
// packed f32x2 helpers (sm_100+ PTX)
// ---------------------------------------------------------------------------
__device__ __forceinline__ unsigned long long pack2(float a, float b) {
    unsigned long long r;
    asm("mov.b64 %0, {%1, %2};" : "=l"(r) : "f"(a), "f"(b));
    return r;
}
__device__ __forceinline__ void fma2(unsigned long long& acc,
                                     unsigned long long a,
                                     unsigned long long b) {
    asm("fma.rn.f32x2 %0, %1, %2, %0;" : "+l"(acc) : "l"(a), "l"(b));
}

// ---------------------------------------------------------------------------
// Kernel 1: support[row][0:64] = x[row][0:256] @ W   (one row per thread)
// ---------------------------------------------------------------------------
__global__ void __launch_bounds__(128)
gemm_kernel(const float* __restrict__ x, const float* __restrict__ w, int rows)
{
    __shared__ __align__(16) float ws[128 * D_OUT];   // 32 KB

    const int row = blockIdx.x * 128 + threadIdx.x;

    unsigned long long acc[32];
#pragma unroll
    for (int i = 0; i < 32; ++i) acc[i] = 0ull;

    for (int half = 0; half < 2; ++half) {
        const float4* wsrc = (const float4*)(w + (size_t)half * 128 * D_OUT);
        float4*       wdst = (float4*)ws;
        for (int i = threadIdx.x; i < 128 * D_OUT / 4; i += 128)
            wdst[i] = wsrc[i];
        __syncthreads();

        if (row < rows) {
            const float4* xr = (const float4*)(x + (size_t)row * D_IN) + half * 32;
#pragma unroll 1
            for (int d4 = 0; d4 < 32; ++d4) {
                const float4 xv = xr[d4];
#pragma unroll
                for (int s = 0; s < 4; ++s) {
                    const float xs = (s == 0) ? xv.x : (s == 1) ? xv.y
                                   : (s == 2) ? xv.z : xv.w;
                    const unsigned long long xp = pack2(xs, xs);
                    const double2* wrow = (const double2*)(ws + (d4 * 4 + s) * D_OUT);
#pragma unroll
                    for (int q = 0; q < 16; ++q) {
                        const double2 wv = wrow[q];   // LDS.128 broadcast
                        fma2(acc[2 * q + 0], xp, __double_as_longlong(wv.x));
                        fma2(acc[2 * q + 1], xp, __double_as_longlong(wv.y));
                    }
                }
            }
        }
        __syncthreads();
    }

    if (row < rows) {
        double* sup = (double*)(g_support + (size_t)row * D_OUT);
#pragma unroll
        for (int q = 0; q < 32; ++q)
            sup[q] = __longlong_as_double(acc[q]);    // bitwise 2x f32 store
    }
}

// ---------------------------------------------------------------------------
// CSR build
// ---------------------------------------------------------------------------
__global__ void zero_deg_kernel(int n)
{
    int i = blockIdx.x * blockDim.x + threadIdx.x;
    if (i < n) g_deg[i] = 0;
}

__global__ void count_kernel(const int* __restrict__ adj_rows, int E)
{
    int e = blockIdx.x * blockDim.x + threadIdx.x;
    if (e < E) atomicAdd(&g_deg[adj_rows[e]], 1);
}

// scan1: per-256-block sums of g_deg
__global__ void __launch_bounds__(256)
scan1_kernel(int n)
{
    __shared__ int s[256];
    int i = blockIdx.x * 256 + threadIdx.x;
    s[threadIdx.x] = (i < n) ? g_deg[i] : 0;
    __syncthreads();
#pragma unroll
    for (int off = 128; off > 0; off >>= 1) {
        if (threadIdx.x < off) s[threadIdx.x] += s[threadIdx.x + off];
        __syncthreads();
    }
    if (threadIdx.x == 0) g_part[blockIdx.x] = s[0];
}

// scan2: exclusive scan of block partials (single block, up to 1024 partials)
__global__ void __launch_bounds__(1024)
scan2_kernel(int nb, int n, int E)
{
    __shared__ int s[1024];
    int t = threadIdx.x;
    int v = (t < nb) ? g_part[t] : 0;
    s[t] = v;
    __syncthreads();
#pragma unroll
    for (int off = 1; off < 1024; off <<= 1) {
        int add = (t >= off) ? s[t - off] : 0;
        __syncthreads();
        s[t] += add;
        __syncthreads();
    }
    if (t < nb) g_pscan[t] = s[t] - v;      // exclusive
    if (t == 0) g_start[n] = E;
}

// scan3: final exclusive scan per block + base; writes g_start and g_cursor
__global__ void __launch_bounds__(256)
scan3_kernel(int n)
{
    __shared__ int s[256];
    int t = threadIdx.x;
    int i = blockIdx.x * 256 + t;
    int d = (i < n) ? g_deg[i] : 0;
    s[t] = d;
    __syncthreads();
#pragma unroll
    for (int off = 1; off < 256; off <<= 1) {
        int add = (t >= off) ? s[t - off] : 0;
        __syncthreads();
        s[t] += add;
        __syncthreads();
    }
    if (i < n) {
        int start = g_pscan[blockIdx.x] + s[t] - d;
        g_start[i]  = start;
        g_cursor[i] = start;
    }
}

__global__ void fill_kernel(const int* __restrict__ adj_rows,
                            const int* __restrict__ adj_cols,
                            const float* __restrict__ adj_vals, int E)
{
    int e = blockIdx.x * blockDim.x + threadIdx.x;
    if (e < E) {
        int r   = adj_rows[e];
        int pos = atomicAdd(&g_cursor[r], 1);
        g_edges[pos] = make_int2(adj_cols[e], __float_as_int(adj_vals[e]));
    }
}

// ---------------------------------------------------------------------------
// Gather: 64 threads per output row; each thread owns one float4 of the
// 256-float row. Register accumulate over CSR edges, fused ReLU store.
// 2-edge unroll -> two independent support gathers in flight per iteration.
// ---------------------------------------------------------------------------
__global__ void __launch_bounds__(256)
gather_kernel(float* __restrict__ out, int n)
{
    const int row = blockIdx.x * 4 + (threadIdx.x >> 6);
    const int j   = threadIdx.x & 63;
    if (row >= n) return;

    const int start = g_start[row];
    const int end   = g_start[row + 1];

    float4 acc = make_float4(0.f, 0.f, 0.f, 0.f);

    int p = start;
    for (; p + 1 < end; p += 2) {
        const int2 e0 = __ldg(&g_edges[p]);
        const int2 e1 = __ldg(&g_edges[p + 1]);
        const float v0 = __int_as_float(e0.y);
        const float v1 = __int_as_float(e1.y);
        const float4 s0 = __ldg((const float4*)(g_support + (size_t)e0.x * 256) + j);
        const float4 s1 = __ldg((const float4*)(g_support + (size_t)e1.x * 256) + j);
        acc.x = fmaf(v0, s0.x, acc.x); acc.y = fmaf(v0, s0.y, acc.y);
        acc.z = fmaf(v0, s0.z, acc.z); acc.w = fmaf(v0, s0.w, acc.w);
        acc.x = fmaf(v1, s1.x, acc.x); acc.y = fmaf(v1, s1.y, acc.y);
        acc.z = fmaf(v1, s1.z, acc.z); acc.w = fmaf(v1, s1.w, acc.w);
    }
    if (p < end) {
        const int2 e0 = __ldg(&g_edges[p]);
        const float v0 = __int_as_float(e0.y);
        const float4 s0 = __ldg((const float4*)(g_support + (size_t)e0.x * 256) + j);
        acc.x = fmaf(v0, s0.x, acc.x); acc.y = fmaf(v0, s0.y, acc.y);
        acc.z = fmaf(v0, s0.z, acc.z); acc.w = fmaf(v0, s0.w, acc.w);
    }

    acc.x = fmaxf(acc.x, 0.f); acc.y = fmaxf(acc.y, 0.f);
    acc.z = fmaxf(acc.z, 0.f); acc.w = fmaxf(acc.w, 0.f);
    ((float4*)(out + (size_t)row * 256))[j] = acc;
}

// ---------------------------------------------------------------------------
// Launch
// inputs (metadata order): x[f32], weight[f32], adj_rows[i32], adj_cols[i32],
//                          adj_vals[f32]; output f32 [N,K,64]
// ---------------------------------------------------------------------------
extern "C" void kernel_launch(void* const* d_in, const int* in_sizes, int n_in,
                              void* d_out, int out_size)
{
    const float* x  = (const float*)d_in[0];
    const float* w  = (const float*)d_in[1];
    const int*   ar = (const int*)d_in[2];
    const int*   ac = (const int*)d_in[3];
    const float* av = (const float*)d_in[4];
    float*       out = (float*)d_out;

    const int rows = in_sizes[0] / D_IN;          // 200000 (N*K)
    const int E    = in_sizes[2];                 // 800000
    const int N    = out_size / 256;              // 50000 (K*D_OUT floats/row)
    const int NB   = (N + 255) / 256;             // scan blocks (<=1024)

    // dense GEMM: support = x @ W
    gemm_kernel<<<(rows + 127) / 128, 128>>>(x, w, rows);

    // CSR build
    zero_deg_kernel<<<(N + 255) / 256, 256>>>(N);
    count_kernel<<<(E + 255) / 256, 256>>>(ar, E);
    scan1_kernel<<<NB, 256>>>(N);
    scan2_kernel<<<1, 1024>>>(NB, N, E);
    scan3_kernel<<<NB, 256>>>(N);
    fill_kernel<<<(E + 255) / 256, 256>>>(ar, ac, av, E);

    // register-accumulating gather with fused ReLU
    gather_kernel<<<(N + 3) / 4, 256>>>(out, N);
}

// round 13
// speedup vs baseline: 2.4477x; 1.8380x over previous
#include <cuda_runtime.h>
#include <cuda_bf16.h>
#include <cstdint>

#define D_IN  256
#define D_OUT 64
#define ROWS_TOTAL 200000   // N*K = 50000*4
#define NMAX  50048
#define EMAX  800000

// ---------------------------------------------------------------------------
// Static device scratch
// ---------------------------------------------------------------------------
__device__ float g_support[(size_t)ROWS_TOTAL * D_OUT];  // 51.2 MB
__device__ int   g_deg[NMAX];
__device__ int   g_start[NMAX + 1];
__device__ int   g_cursor[NMAX];
__device__ int2  g_edges[EMAX];
__device__ int   g_part[1024];
__device__ int   g_pscan[1024];
// B fragments of W^T in mma.sync register layout:
// [kstep(16)][ntile(8)][lane(32)] -> uint4 {b0_hi, b1_hi, b0_lo, b1_lo}
__device__ __align__(16) uint4 g_bfrag[16 * 8 * 32];     // 64 KB

// ---------------------------------------------------------------------------
// MMA helpers (plain sm_80-level PTX: valid for compute_103 target)
// ---------------------------------------------------------------------------
__device__ __forceinline__ uint32_t smem_u32(const void* p) {
    uint32_t a;
    asm("{ .reg .u64 t; cvta.to.shared.u64 t, %1; cvt.u32.u64 %0, t; }" : "=r"(a) : "l"(p));
    return a;
}
__device__ __forceinline__ void ldsm_x4(uint32_t* r, uint32_t addr) {
    asm volatile("ldmatrix.sync.aligned.m8n8.x4.shared.b16 {%0,%1,%2,%3}, [%4];"
                 : "=r"(r[0]), "=r"(r[1]), "=r"(r[2]), "=r"(r[3]) : "r"(addr));
}
__device__ __forceinline__ void mma16816(float* c, const uint32_t* a,
                                         uint32_t b0, uint32_t b1) {
    asm volatile(
        "mma.sync.aligned.m16n8k16.row.col.f32.bf16.bf16.f32 "
        "{%0,%1,%2,%3}, {%4,%5,%6,%7}, {%8,%9}, {%0,%1,%2,%3};"
        : "+f"(c[0]), "+f"(c[1]), "+f"(c[2]), "+f"(c[3])
        : "r"(a[0]), "r"(a[1]), "r"(a[2]), "r"(a[3]), "r"(b0), "r"(b1));
}

// ---------------------------------------------------------------------------
// B prep: W[256,64] -> hi/lo bf16 fragments in mma register layout
// b0 holds B[k0,k0+1][n], b1 holds B[k0+8,k0+9][n]; k0 = ks*16+(lane&3)*2,
// n = ntile*8 + lane/4.  (B = W^T, col-major operand of m16n8k16)
// ---------------------------------------------------------------------------
__global__ void bprep_kernel(const float* __restrict__ w)
{
    int i = blockIdx.x * 256 + threadIdx.x;
    if (i >= 16 * 8 * 32) return;
    int lane = i & 31;
    int n  = ((i >> 5) & 7) * 8 + (lane >> 2);
    int k0 = (i >> 8) * 16 + (lane & 3) * 2;

    float v00 = w[(k0    ) * 64 + n];
    float v01 = w[(k0 + 1) * 64 + n];
    float v10 = w[(k0 + 8) * 64 + n];
    float v11 = w[(k0 + 9) * 64 + n];

    __nv_bfloat162 h0 = __floats2bfloat162_rn(v00, v01);
    __nv_bfloat162 h1 = __floats2bfloat162_rn(v10, v11);
    float2 f0 = __bfloat1622float2(h0);
    float2 f1 = __bfloat1622float2(h1);
    __nv_bfloat162 l0 = __floats2bfloat162_rn(v00 - f0.x, v01 - f0.y);
    __nv_bfloat162 l1 = __floats2bfloat162_rn(v10 - f1.x, v11 - f1.y);

    uint4 r;
    r.x = *(uint32_t*)&h0;  r.y = *(uint32_t*)&h1;
    r.z = *(uint32_t*)&l0;  r.w = *(uint32_t*)&l1;
    g_bfrag[i] = r;
}

// ---------------------------------------------------------------------------
// GEMM via mma.sync bf16 hi/lo split: support[64-row tile][64] = x_tile @ W
// Block: 64 rows, 128 threads (4 warps x 16 rows). A staged in smem as
// bf16 hi/lo with 264-element row stride (conflict-free ldmatrix).
// ---------------------------------------------------------------------------
#define AROW 264                       // elements; 528-byte stride
#define A_IMG (64 * AROW * 2)          // 33792 bytes per image
#define GEMM_SMEM (2 * A_IMG)          // 67584 bytes

__global__ void __launch_bounds__(128, 3)
gemm_mma_kernel(const float* __restrict__ x)
{
    extern __shared__ __align__(16) unsigned char smem[];
    __nv_bfloat16* a_hi = (__nv_bfloat16*)smem;
    __nv_bfloat16* a_lo = (__nv_bfloat16*)(smem + A_IMG);

    const int tid  = threadIdx.x;
    const int wid  = tid >> 5;
    const int lane = tid & 31;
    const int m0   = blockIdx.x * 64;

    // --- load x tile [64][256] f32 -> hi/lo bf16 smem ---
    const float4* xs = (const float4*)x + (size_t)m0 * 64;
    #pragma unroll 4
    for (int i = tid; i < 4096; i += 128) {
        const int r  = i >> 6;
        const int c4 = i & 63;
        float4 v = xs[(size_t)r * 64 + c4];

        __nv_bfloat162 h01 = __floats2bfloat162_rn(v.x, v.y);
        __nv_bfloat162 h23 = __floats2bfloat162_rn(v.z, v.w);
        float2 f01 = __bfloat1622float2(h01);
        float2 f23 = __bfloat1622float2(h23);
        __nv_bfloat162 l01 = __floats2bfloat162_rn(v.x - f01.x, v.y - f01.y);
        __nv_bfloat162 l23 = __floats2bfloat162_rn(v.z - f23.x, v.w - f23.y);

        uint32_t* dh = (uint32_t*)(a_hi + r * AROW + c4 * 4);
        uint32_t* dl = (uint32_t*)(a_lo + r * AROW + c4 * 4);
        dh[0] = *(uint32_t*)&h01;  dh[1] = *(uint32_t*)&h23;
        dl[0] = *(uint32_t*)&l01;  dl[1] = *(uint32_t*)&l23;
    }
    __syncthreads();

    // --- per-warp m16n64 tile, K=256 in 16 k-steps ---
    // ldmatrix lane address: mat = lane>>3
    //   row = wid*16 + (lane&7) + ((mat&1)<<3), col-elems = (mat>>1)*8
    const int mat = lane >> 3;
    const int ar  = (wid << 4) + (lane & 7) + ((mat & 1) << 3);
    const uint32_t aoff = (uint32_t)(ar * AROW + (mat >> 1) * 8) * 2u;
    uint32_t addr_hi = smem_u32(a_hi) + aoff;
    uint32_t addr_lo = smem_u32(a_lo) + aoff;

    float c[8][4];
    #pragma unroll
    for (int nt = 0; nt < 8; ++nt)
        c[nt][0] = c[nt][1] = c[nt][2] = c[nt][3] = 0.f;

    #pragma unroll 1
    for (int ks = 0; ks < 16; ++ks) {
        uint32_t ah[4], al[4];
        ldsm_x4(ah, addr_hi + ks * 32);
        ldsm_x4(al, addr_lo + ks * 32);
        const uint4* bf = g_bfrag + ks * 256 + lane;
        #pragma unroll
        for (int nt = 0; nt < 8; ++nt) {
            const uint4 b = __ldg(bf + nt * 32);
            mma16816(c[nt], ah, b.x, b.y);   // Ahi * Bhi
            mma16816(c[nt], ah, b.z, b.w);   // Ahi * Blo
            mma16816(c[nt], al, b.x, b.y);   // Alo * Bhi
        }
    }

    // --- epilogue: fragment -> g_support (float2 stores) ---
    const int r0 = m0 + (wid << 4) + (lane >> 2);
    const int cb = (lane & 3) * 2;
    #pragma unroll
    for (int nt = 0; nt < 8; ++nt) {
        const int col = nt * 8 + cb;
        *(float2*)(g_support + (size_t)r0 * 64 + col)       = make_float2(c[nt][0], c[nt][1]);
        *(float2*)(g_support + (size_t)(r0 + 8) * 64 + col) = make_float2(c[nt][2], c[nt][3]);
    }
}

// ---------------------------------------------------------------------------
// CSR build
// ---------------------------------------------------------------------------
__global__ void zero_deg_kernel(int n)
{
    int i = blockIdx.x * blockDim.x + threadIdx.x;
    if (i < n) g_deg[i] = 0;
}

__global__ void count_kernel(const int* __restrict__ adj_rows, int E)
{
    int e = blockIdx.x * blockDim.x + threadIdx.x;
    if (e < E) atomicAdd(&g_deg[adj_rows[e]], 1);
}

__global__ void __launch_bounds__(256)
scan1_kernel(int n)
{
    __shared__ int s[256];
    int i = blockIdx.x * 256 + threadIdx.x;
    s[threadIdx.x] = (i < n) ? g_deg[i] : 0;
    __syncthreads();
#pragma unroll
    for (int off = 128; off > 0; off >>= 1) {
        if (threadIdx.x < off) s[threadIdx.x] += s[threadIdx.x + off];
        __syncthreads();
    }
    if (threadIdx.x == 0) g_part[blockIdx.x] = s[0];
}

__global__ void __launch_bounds__(1024)
scan2_kernel(int nb, int n, int E)
{
    __shared__ int s[1024];
    int t = threadIdx.x;
    int v = (t < nb) ? g_part[t] : 0;
    s[t] = v;
    __syncthreads();
#pragma unroll
    for (int off = 1; off < 1024; off <<= 1) {
        int add = (t >= off) ? s[t - off] : 0;
        __syncthreads();
        s[t] += add;
        __syncthreads();
    }
    if (t < nb) g_pscan[t] = s[t] - v;
    if (t == 0) g_start[n] = E;
}

__global__ void __launch_bounds__(256)
scan3_kernel(int n)
{
    __shared__ int s[256];
    int t = threadIdx.x;
    int i = blockIdx.x * 256 + t;
    int d = (i < n) ? g_deg[i] : 0;
    s[t] = d;
    __syncthreads();
#pragma unroll
    for (int off = 1; off < 256; off <<= 1) {
        int add = (t >= off) ? s[t - off] : 0;
        __syncthreads();
        s[t] += add;
        __syncthreads();
    }
    if (i < n) {
        int start = g_pscan[blockIdx.x] + s[t] - d;
        g_start[i]  = start;
        g_cursor[i] = start;
    }
}

__global__ void fill_kernel(const int* __restrict__ adj_rows,
                            const int* __restrict__ adj_cols,
                            const float* __restrict__ adj_vals, int E)
{
    int e = blockIdx.x * blockDim.x + threadIdx.x;
    if (e < E) {
        int r   = adj_rows[e];
        int pos = atomicAdd(&g_cursor[r], 1);
        g_edges[pos] = make_int2(adj_cols[e], __float_as_int(adj_vals[e]));
    }
}

// ---------------------------------------------------------------------------
// Gather with fused ReLU. 64 threads per output row; 4-edge unroll for MLP.
// ---------------------------------------------------------------------------
__global__ void __launch_bounds__(256)
gather_kernel(float* __restrict__ out, int n)
{
    const int row = blockIdx.x * 4 + (threadIdx.x >> 6);
    const int j   = threadIdx.x & 63;
    if (row >= n) return;

    const int start = g_start[row];
    const int end   = g_start[row + 1];

    float4 acc = make_float4(0.f, 0.f, 0.f, 0.f);

    int p = start;
    for (; p + 3 < end; p += 4) {
        const int2 e0 = __ldg(&g_edges[p]);
        const int2 e1 = __ldg(&g_edges[p + 1]);
        const int2 e2 = __ldg(&g_edges[p + 2]);
        const int2 e3 = __ldg(&g_edges[p + 3]);
        const float4 s0 = __ldg((const float4*)(g_support + (size_t)e0.x * 256) + j);
        const float4 s1 = __ldg((const float4*)(g_support + (size_t)e1.x * 256) + j);
        const float4 s2 = __ldg((const float4*)(g_support + (size_t)e2.x * 256) + j);
        const float4 s3 = __ldg((const float4*)(g_support + (size_t)e3.x * 256) + j);
        const float v0 = __int_as_float(e0.y), v1 = __int_as_float(e1.y);
        const float v2 = __int_as_float(e2.y), v3 = __int_as_float(e3.y);
        acc.x = fmaf(v0, s0.x, acc.x); acc.y = fmaf(v0, s0.y, acc.y);
        acc.z = fmaf(v0, s0.z, acc.z); acc.w = fmaf(v0, s0.w, acc.w);
        acc.x = fmaf(v1, s1.x, acc.x); acc.y = fmaf(v1, s1.y, acc.y);
        acc.z = fmaf(v1, s1.z, acc.z); acc.w = fmaf(v1, s1.w, acc.w);
        acc.x = fmaf(v2, s2.x, acc.x); acc.y = fmaf(v2, s2.y, acc.y);
        acc.z = fmaf(v2, s2.z, acc.z); acc.w = fmaf(v2, s2.w, acc.w);
        acc.x = fmaf(v3, s3.x, acc.x); acc.y = fmaf(v3, s3.y, acc.y);
        acc.z = fmaf(v3, s3.z, acc.z); acc.w = fmaf(v3, s3.w, acc.w);
    }
    for (; p < end; ++p) {
        const int2 e0 = __ldg(&g_edges[p]);
        const float v0 = __int_as_float(e0.y);
        const float4 s0 = __ldg((const float4*)(g_support + (size_t)e0.x * 256) + j);
        acc.x = fmaf(v0, s0.x, acc.x); acc.y = fmaf(v0, s0.y, acc.y);
        acc.z = fmaf(v0, s0.z, acc.z); acc.w = fmaf(v0, s0.w, acc.w);
    }

    acc.x = fmaxf(acc.x, 0.f); acc.y = fmaxf(acc.y, 0.f);
    acc.z = fmaxf(acc.z, 0.f); acc.w = fmaxf(acc.w, 0.f);
    ((float4*)(out + (size_t)row * 256))[j] = acc;
}

// ---------------------------------------------------------------------------
// Launch: single stream, no statics, fully capture-safe.
// ---------------------------------------------------------------------------
extern "C" void kernel_launch(void* const* d_in, const int* in_sizes, int n_in,
                              void* d_out, int out_size)
{
    const float* x  = (const float*)d_in[0];
    const float* w  = (const float*)d_in[1];
    const int*   ar = (const int*)d_in[2];
    const int*   ac = (const int*)d_in[3];
    const float* av = (const float*)d_in[4];
    float*       out = (float*)d_out;

    const int rows = in_sizes[0] / D_IN;          // 200000
    const int E    = in_sizes[2];                 // 800000
    const int N    = out_size / 256;              // 50000
    const int NB   = (N + 255) / 256;

    cudaFuncSetAttribute(gemm_mma_kernel,
                         cudaFuncAttributeMaxDynamicSharedMemorySize, GEMM_SMEM);

    // GEMM (tensor cores via mma.sync, bf16 hi/lo split)
    bprep_kernel<<<16, 256>>>(w);
    gemm_mma_kernel<<<rows / 64, 128, GEMM_SMEM>>>(x);

    // CSR build
    zero_deg_kernel<<<(N + 255) / 256, 256>>>(N);
    count_kernel<<<(E + 255) / 256, 256>>>(ar, E);
    scan1_kernel<<<NB, 256>>>(N);
    scan2_kernel<<<1, 1024>>>(NB, N, E);
    scan3_kernel<<<NB, 256>>>(N);
    fill_kernel<<<(E + 255) / 256, 256>>>(ar, ac, av, E);

    // register-accumulating gather with fused ReLU
    gather_kernel<<<(N + 3) / 4, 256>>>(out, N);
}